// round 10
// baseline (speedup 1.0000x reference)
#include <cuda_runtime.h>
#include <cuda_fp16.h>
#include <math.h>

#define DIM 512
#define HID 2048
#define NLAYERS 4
#define VOCAB 32000
#define BB 2
#define SS 2048
#define M_TOT (BB*SS)   // 4096

// ---------------- scratch (device globals; no allocation allowed) ----------------
__device__ float g_x [M_TOT*DIM];
__device__ float g_qg[M_TOT*1024];       // [q | g] fused, row stride 1024
__device__ float g_a [M_TOT*HID];
__device__ float g_nl[M_TOT];
__device__ float g_nlmax[NLAYERS*64];    // per-layer, 64 tiles (both batches)
// packed split-fp16 (1 u32 per element)
__device__ unsigned g_h_p [M_TOT*DIM];
__device__ unsigned g_f_p [M_TOT*DIM];
__device__ unsigned g_ao_p[M_TOT*DIM];
__device__ unsigned g_t_p [M_TOT*HID];
__device__ unsigned g_wqg_p [NLAYERS*1024*DIM];   // q rows then g rows per layer
__device__ unsigned g_wout_p[NLAYERS*DIM*DIM];
// packed plain-fp16 (0.5 u32 per element)
__device__ unsigned g_whh_p [NLAYERS*HID*DIM/2];
__device__ unsigned g_wgg_p [NLAYERS*HID*DIM/2];
__device__ unsigned g_wo_p  [NLAYERS*DIM*HID/2];
__device__ unsigned g_hf_p [M_TOT*DIM/2];
__device__ unsigned g_emb_p[VOCAB*DIM/2];

__device__ __forceinline__ float silu_f(float v) {
    return v / (1.0f + __expf(-v));
}

__device__ __forceinline__ unsigned hpack(__half a, __half b) {
    __half2 t = __halves2half2(a, b);
    return *reinterpret_cast<unsigned*>(&t);
}

__device__ __forceinline__ uint2 split2(float x0, float x1) {
    __half h0 = __float2half_rn(x0), h1 = __float2half_rn(x1);
    unsigned H = hpack(h0, h1);
    unsigned L = hpack(__float2half_rn(x0 - __half2float(h0)),
                       __float2half_rn(x1 - __half2float(h1)));
    return make_uint2(H, L);
}

__device__ __forceinline__ void mma_f16(float* c, const unsigned* a, const unsigned* b) {
    asm volatile(
        "mma.sync.aligned.m16n8k16.row.col.f32.f16.f16.f32 "
        "{%0,%1,%2,%3}, {%4,%5,%6,%7}, {%8,%9}, {%0,%1,%2,%3};"
        : "+f"(c[0]), "+f"(c[1]), "+f"(c[2]), "+f"(c[3])
        : "r"(a[0]), "r"(a[1]), "r"(a[2]), "r"(a[3]), "r"(b[0]), "r"(b[1]));
}

__device__ __forceinline__ void cp16(unsigned* dst, const unsigned* src) {
    unsigned d = (unsigned)__cvta_generic_to_shared(dst);
    asm volatile("cp.async.cg.shared.global [%0], [%1], 16;" :: "r"(d), "l"(src) : "memory");
}
#define CPA_COMMIT asm volatile("cp.async.commit_group;" ::: "memory")
#define CPA_WAIT1  asm volatile("cp.async.wait_group 1;" ::: "memory")

// layout helpers: within a 16-k chunk, pair p (k=2p,2p+1)
__device__ __forceinline__ int spos(int p) { return (p & 3) * 4 + ((p >> 2) << 1); }
__device__ __forceinline__ int ppos(int p) { return (p & 3) * 2 + (p >> 2); }

// ---------------- fused weight conversion (single launch) ----------------
template<int QGOFF>
__device__ __forceinline__ void conv_split_one(const float* __restrict__ src,
                                               unsigned* __restrict__ dst,
                                               long idx, int K) {
    int perRow = K >> 2;
    long row = idx / perRow;
    int rem = (int)(idx - row * perRow);
    int kc = rem >> 2, i4 = rem & 3;
    float4 v = reinterpret_cast<const float4*>(src)[idx];
    long drow = (QGOFF >= 0) ? ((row >> 9) * 1024 + QGOFF + (row & 511)) : row;
    unsigned* base = dst + drow * (long)K + kc * 16;
    int p0 = 2 * i4;
    *reinterpret_cast<uint2*>(base + spos(p0))     = split2(v.x, v.y);
    *reinterpret_cast<uint2*>(base + spos(p0 + 1)) = split2(v.z, v.w);
}
__device__ __forceinline__ void conv_plain_one(const float* __restrict__ src,
                                               unsigned* __restrict__ dst,
                                               long idx, int K) {
    int perRow = K >> 2;
    long row = idx / perRow;
    int rem = (int)(idx - row * perRow);
    int kc = rem >> 2, i4 = rem & 3;
    float4 v = reinterpret_cast<const float4*>(src)[idx];
    unsigned* base = dst + row * (long)(K >> 1) + kc * 8;
    int p0 = 2 * i4;
    base[ppos(p0)]     = hpack(__float2half_rn(v.x), __float2half_rn(v.y));
    base[ppos(p0 + 1)] = hpack(__float2half_rn(v.z), __float2half_rn(v.w));
}

#define CB_S (NLAYERS*DIM*DIM/4/256)   // 1024
#define CB_H (NLAYERS*HID*DIM/4/256)   // 4096
#define CB_V ((long)VOCAB*DIM/4/256)   // 16000
#define CB_TOTAL (3*CB_S + 3*CB_H + (int)CB_V)

__global__ void convert_all(
    const float* __restrict__ wq_s,  unsigned* __restrict__ wqg_d,
    const float* __restrict__ wg_s,
    const float* __restrict__ wo_s,  unsigned* __restrict__ wo_d,
    const float* __restrict__ whh_s, unsigned* __restrict__ whh_d,
    const float* __restrict__ wgg_s, unsigned* __restrict__ wgg_d,
    const float* __restrict__ wop_s, unsigned* __restrict__ wop_d,
    const float* __restrict__ emb_s, unsigned* __restrict__ emb_d,
    float* __restrict__ NM)
{
    int b = blockIdx.x;
    if (b == 0 && threadIdx.x < NLAYERS*64)
        NM[threadIdx.x] = __int_as_float(0x7F800000);   // +inf (identity for min-int)
    if (b < CB_S) {
        conv_split_one<0>(wq_s, wqg_d, (long)b * 256 + threadIdx.x, DIM);
    } else if (b < 2*CB_S) {
        conv_split_one<512>(wg_s, wqg_d, (long)(b - CB_S) * 256 + threadIdx.x, DIM);
    } else if (b < 3*CB_S) {
        conv_split_one<-1>(wo_s, wo_d, (long)(b - 2*CB_S) * 256 + threadIdx.x, DIM);
    } else if (b < 3*CB_S + CB_H) {
        conv_plain_one(whh_s, whh_d, (long)(b - 3*CB_S) * 256 + threadIdx.x, DIM);
    } else if (b < 3*CB_S + 2*CB_H) {
        conv_plain_one(wgg_s, wgg_d, (long)(b - 3*CB_S - CB_H) * 256 + threadIdx.x, DIM);
    } else if (b < 3*CB_S + 3*CB_H) {
        conv_plain_one(wop_s, wop_d, (long)(b - 3*CB_S - 2*CB_H) * 256 + threadIdx.x, HID);
    } else {
        conv_plain_one(emb_s, emb_d, (long)(b - 3*CB_S - 3*CB_H) * 256 + threadIdx.x, DIM);
    }
}

// ---------------- embedding gather ----------------
__global__ void embed_kernel(const int* __restrict__ tok,
                             const float* __restrict__ emb,
                             float* __restrict__ X) {
    long idx = (long)blockIdx.x * 256 + threadIdx.x;
    int row = (int)(idx >> 7);
    int c   = (int)(idx & 127);
    int t   = tok[row];
    reinterpret_cast<float4*>(X)[idx] =
        reinterpret_cast<const float4*>(emb + (long)t * DIM)[c];
}

// ---------------- RMSNorm -> packed output (+ fused lambda + nlmax atomic) ----------
template<bool LAM, int PACK>
__global__ void rmsnorm_kernel(const float* __restrict__ X,
                               const float* __restrict__ w,
                               const float* __restrict__ lam,
                               unsigned* __restrict__ Hp,
                               float* __restrict__ NL,
                               float* __restrict__ NM) {
    __shared__ float sb[4];
    __shared__ float s_scale;
    const int row = blockIdx.x;
    const int t = threadIdx.x;
    float4 v = reinterpret_cast<const float4*>(X + (long)row * DIM)[t];
    float ss = v.x*v.x + v.y*v.y + v.z*v.z + v.w*v.w;
    #pragma unroll
    for (int o = 16; o > 0; o >>= 1) ss += __shfl_down_sync(0xffffffffu, ss, o);
    if ((t & 31) == 0) sb[t >> 5] = ss;
    __syncthreads();
    if (t == 0) {
        float tot = sb[0] + sb[1] + sb[2] + sb[3];
        s_scale = rsqrtf(tot / (float)DIM + 1e-6f);
    }
    __syncthreads();
    const float sc = s_scale;
    float4 wv = reinterpret_cast<const float4*>(w)[t];
    float4 h;
    h.x = v.x * sc * wv.x;
    h.y = v.y * sc * wv.y;
    h.z = v.z * sc * wv.z;
    h.w = v.w * sc * wv.w;
    const int kc = t >> 2, i4 = t & 3;
    const int p0 = 2 * i4;
    if (PACK == 0) {
        unsigned* base = Hp + (long)row * DIM + kc * 16;
        *reinterpret_cast<uint2*>(base + spos(p0))     = split2(h.x, h.y);
        *reinterpret_cast<uint2*>(base + spos(p0 + 1)) = split2(h.z, h.w);
    } else {
        unsigned* base = Hp + (long)row * (DIM / 2) + kc * 8;
        base[ppos(p0)]     = hpack(__float2half_rn(h.x), __float2half_rn(h.y));
        base[ppos(p0 + 1)] = hpack(__float2half_rn(h.z), __float2half_rn(h.w));
    }
    if (LAM) {
        float4 lv = reinterpret_cast<const float4*>(lam)[t];
        float d = h.x*lv.x + h.y*lv.y + h.z*lv.z + h.w*lv.w;
        #pragma unroll
        for (int o = 16; o > 0; o >>= 1) d += __shfl_down_sync(0xffffffffu, d, o);
        __syncthreads();
        if ((t & 31) == 0) sb[t >> 5] = d;
        __syncthreads();
        if (t == 0) {
            float dot = sb[0] + sb[1] + sb[2] + sb[3];
            float nl = (dot >= 0.0f) ? -log1pf(expf(-dot))
                                     : (dot - log1pf(expf(dot)));
            NL[row] = nl;
            // nl < 0 always: signed-int min == float max for negative floats
            atomicMin(reinterpret_cast<int*>(NM) + (row >> 6), __float_as_int(nl));
        }
    }
}

// ---------------- tensor-core NT GEMM, cp.async 3-stage ----------------------------
// ASP/BSP: operand split (hi+lo) vs plain fp16. MT: 128 or 256 (256 only plain).
// EPI: 0 C=acc | 1 C+=acc | 2 C+=acc*E | 3 CP=packsplit(silu(acc)*E).  ES: E row stride.
template<int ASP, int BSP, int MT, int EPI>
__global__ void __launch_bounds__(256) gemm_tc(
    const unsigned* __restrict__ A, const unsigned* __restrict__ W,
    float* __restrict__ C, const float* __restrict__ E,
    unsigned* __restrict__ CP, int M, int N, int K, int ES)
{
    constexpr int NT = 128;
    constexpr int RSA = ASP ? 16 : 8;
    constexpr int RSB = BSP ? 16 : 8;
    constexpr int ASZ = MT * 2 * RSA;
    constexpr int BSZ = NT * 2 * RSB;
    constexpr int WN  = (MT == 128) ? 4 : 2;     // warps along N
    constexpr int NI  = NT / (WN * 8);           // 4 or 8
    extern __shared__ unsigned sm[];

    const int tid  = threadIdx.x;
    const int lane = tid & 31;
    const int gr   = lane >> 2;
    const int tc   = lane & 3;
    const int warp = tid >> 5;
    const int wm   = warp / WN;
    const int wn   = warp % WN;
    const long bm = (long)blockIdx.y * MT;
    const long bn = (long)blockIdx.x * NT;
    const long KuA = ASP ? K : (K >> 1);
    const long KuB = BSP ? K : (K >> 1);

    float acc[4][NI][4] = {};

    auto issue = [&](int s, int it) {
        unsigned* Sa = sm + s * (ASZ + BSZ);
        unsigned* Sb = Sa + ASZ;
        int row = tid >> 1, half = tid & 1;
        if (MT == 256) {
            // plain only
            const unsigned* s0 = A + (bm + row) * KuA + it * 16 + half * 8;
            unsigned* d0 = Sa + half * (256 * 8) + row * 8;
            cp16(d0, s0); cp16(d0 + 4, s0 + 4);
            const unsigned* s1 = A + (bm + row + 128) * KuA + it * 16 + half * 8;
            unsigned* d1 = Sa + half * (256 * 8) + (row + 128) * 8;
            cp16(d1, s1); cp16(d1 + 4, s1 + 4);
            const unsigned* sbp = W + (bn + row) * KuB + it * 16 + half * 8;
            unsigned* dbp = Sb + half * (128 * 8) + row * 8;
            cp16(dbp, sbp); cp16(dbp + 4, sbp + 4);
        } else {
            if (ASP) {
                const unsigned* src = A + (bm + row) * KuA + it * 32 + half * 16;
                unsigned* dst = Sa + half * (128 * 16) + row * 16;
                cp16(dst, src); cp16(dst + 4, src + 4);
                cp16(dst + 8, src + 8); cp16(dst + 12, src + 12);
            } else {
                const unsigned* src = A + (bm + row) * KuA + it * 16 + half * 8;
                unsigned* dst = Sa + half * (128 * 8) + row * 8;
                cp16(dst, src); cp16(dst + 4, src + 4);
            }
            if (BSP) {
                const unsigned* sbp = W + (bn + row) * KuB + it * 32 + half * 16;
                unsigned* dbp = Sb + half * (128 * 16) + row * 16;
                cp16(dbp, sbp); cp16(dbp + 4, sbp + 4);
                cp16(dbp + 8, sbp + 8); cp16(dbp + 12, sbp + 12);
            } else {
                const unsigned* sbp = W + (bn + row) * KuB + it * 16 + half * 8;
                unsigned* dbp = Sb + half * (128 * 8) + row * 8;
                cp16(dbp, sbp); cp16(dbp + 4, sbp + 4);
            }
        }
    };

    const int nIter = K >> 5;
    issue(0, 0); CPA_COMMIT;
    issue(1, 1); CPA_COMMIT;

    for (int it = 0; it < nIter; it++) {
        CPA_WAIT1;
        __syncthreads();
        if (it + 2 < nIter) issue((it + 2) % 3, it + 2);
        CPA_COMMIT;

        const unsigned* Sa = sm + (it % 3) * (ASZ + BSZ);
        const unsigned* Sb = Sa + ASZ;

        #pragma unroll
        for (int sc = 0; sc < 2; sc++) {
            const unsigned* Asc = Sa + sc * (MT * RSA);
            const unsigned* Bsc = Sb + sc * (NT * RSB);

            unsigned bhi[NI][2], blo[NI][2];
            #pragma unroll
            for (int ni = 0; ni < NI; ni++) {
                if (BSP) {
                    uint4 f = *reinterpret_cast<const uint4*>(
                        Bsc + (wn * (NT/WN) + ni * 8 + gr) * 16 + tc * 4);
                    bhi[ni][0] = f.x; blo[ni][0] = f.y;
                    bhi[ni][1] = f.z; blo[ni][1] = f.w;
                } else {
                    uint2 f = *reinterpret_cast<const uint2*>(
                        Bsc + (wn * (NT/WN) + ni * 8 + gr) * 8 + tc * 2);
                    bhi[ni][0] = f.x; bhi[ni][1] = f.y;
                }
            }
            unsigned ahi[4][4], alo[4][4];
            #pragma unroll
            for (int mi = 0; mi < 4; mi++) {
                int r = wm * 64 + mi * 16 + gr;
                if (ASP) {
                    uint4 f0 = *reinterpret_cast<const uint4*>(Asc + r * 16 + tc * 4);
                    uint4 f1 = *reinterpret_cast<const uint4*>(Asc + (r + 8) * 16 + tc * 4);
                    ahi[mi][0] = f0.x; ahi[mi][1] = f1.x; ahi[mi][2] = f0.z; ahi[mi][3] = f1.z;
                    alo[mi][0] = f0.y; alo[mi][1] = f1.y; alo[mi][2] = f0.w; alo[mi][3] = f1.w;
                } else {
                    uint2 f0 = *reinterpret_cast<const uint2*>(Asc + r * 8 + tc * 2);
                    uint2 f1 = *reinterpret_cast<const uint2*>(Asc + (r + 8) * 8 + tc * 2);
                    ahi[mi][0] = f0.x; ahi[mi][1] = f1.x; ahi[mi][2] = f0.y; ahi[mi][3] = f1.y;
                }
            }

            #pragma unroll
            for (int mi = 0; mi < 4; mi++)
                #pragma unroll
                for (int ni = 0; ni < NI; ni++)
                    mma_f16(acc[mi][ni], ahi[mi], bhi[ni]);
            if (ASP) {
                #pragma unroll
                for (int mi = 0; mi < 4; mi++)
                    #pragma unroll
                    for (int ni = 0; ni < NI; ni++)
                        mma_f16(acc[mi][ni], alo[mi], bhi[ni]);
            }
            if (BSP) {
                #pragma unroll
                for (int mi = 0; mi < 4; mi++)
                    #pragma unroll
                    for (int ni = 0; ni < NI; ni++)
                        mma_f16(acc[mi][ni], ahi[mi], blo[ni]);
            }
        }
    }

    // epilogue
    #pragma unroll
    for (int mi = 0; mi < 4; mi++) {
        #pragma unroll
        for (int ni = 0; ni < NI; ni++) {
            long row = bm + wm * 64 + mi * 16 + gr;
            int col = (int)bn + wn * (NT/WN) + ni * 8 + tc * 2;
            float* a = acc[mi][ni];
            long i0 = row * (long)N + col;
            long i1 = (row + 8) * (long)N + col;
            if (EPI == 3) {
                long e0i = row * (long)ES + col, e1i = (row + 8) * (long)ES + col;
                float2 e0 = *reinterpret_cast<const float2*>(&E[e0i]);
                float2 e1 = *reinterpret_cast<const float2*>(&E[e1i]);
                uint2 w0 = split2(silu_f(a[0]) * e0.x, silu_f(a[1]) * e0.y);
                uint2 w1 = split2(silu_f(a[2]) * e1.x, silu_f(a[3]) * e1.y);
                int kc = col >> 4, p = (col >> 1) & 7;
                int pos = spos(p);
                *reinterpret_cast<uint2*>(CP + row * (long)N + kc * 16 + pos)       = w0;
                *reinterpret_cast<uint2*>(CP + (row + 8) * (long)N + kc * 16 + pos) = w1;
            } else {
                float2 o0, o1;
                if (EPI == 0) {
                    o0 = make_float2(a[0], a[1]);
                    o1 = make_float2(a[2], a[3]);
                } else if (EPI == 1) {
                    float2 c0 = *reinterpret_cast<float2*>(&C[i0]);
                    float2 c1 = *reinterpret_cast<float2*>(&C[i1]);
                    o0 = make_float2(c0.x + a[0], c0.y + a[1]);
                    o1 = make_float2(c1.x + a[2], c1.y + a[3]);
                } else {
                    long e0i = row * (long)ES + col, e1i = (row + 8) * (long)ES + col;
                    float2 c0 = *reinterpret_cast<float2*>(&C[i0]);
                    float2 c1 = *reinterpret_cast<float2*>(&C[i1]);
                    float2 e0 = *reinterpret_cast<const float2*>(&E[e0i]);
                    float2 e1 = *reinterpret_cast<const float2*>(&E[e1i]);
                    o0 = make_float2(c0.x + a[0]*e0.x, c0.y + a[1]*e0.y);
                    o1 = make_float2(c1.x + a[2]*e1.x, c1.y + a[3]*e1.y);
                }
                *reinterpret_cast<float2*>(&C[i0]) = o0;
                *reinterpret_cast<float2*>(&C[i1]) = o1;
            }
        }
    }
}

// ---------------- decay attention with band pruning; emits packed silu(out) ---------
__global__ void __launch_bounds__(256) decay_attn(
    const float* __restrict__ Q, const float* __restrict__ NLv,
    const float* __restrict__ NM, unsigned* __restrict__ AOp, int QS)
{
    const int it = blockIdx.x;
    const int dt = blockIdx.y;
    const int b  = blockIdx.z;
    const float* q  = Q + (long)b*SS*QS + dt*64;
    const float* nl = NLv + (long)b*SS;
    const float* nlmax = NM + b*(SS/64);
    __shared__ float qs[64][64];
    __shared__ float nls[64];
    __shared__ float sgs[64];
    const int tid = threadIdx.x;
    const int tx = tid & 15, ty = tid >> 4;
    float acc[4][4] = {};
    const int i0 = it*64 + ty*4;

    for (int jt = 0; jt <= it; jt++) {
        if (jt < it) {
            float dmin = (float)(it*64 - (jt*64 + 63));
            if (nlmax[jt] * dmin < -25.0f) continue;
        }
        {
            int r = tid >> 4;
            int c = (tid & 15) * 4;
            #pragma unroll
            for (int rr = 0; rr < 64; rr += 16) {
                float4 v = *reinterpret_cast<const float4*>(
                    q + (long)(jt*64 + r + rr) * QS + c);
                *reinterpret_cast<float4*>(&qs[r + rr][c]) = v;
            }
        }
        if (tid < 64) {
            float xv = nl[jt*64 + tid];
            nls[tid] = xv;
            sgs[tid] = expf(xv);
        }
        __syncthreads();

        if (jt < it) {
            #pragma unroll 2
            for (int j = 0; j < 64; j++) {
                float s = sgs[j];
                float w = expf(nls[j] * (float)(i0 - (jt*64 + j)));
                float4 qv = *reinterpret_cast<const float4*>(&qs[j][tx*4]);
                #pragma unroll
                for (int ii = 0; ii < 4; ii++) {
                    acc[ii][0] += w * qv.x;
                    acc[ii][1] += w * qv.y;
                    acc[ii][2] += w * qv.z;
                    acc[ii][3] += w * qv.w;
                    w *= s;
                }
            }
        } else {
            for (int j = 0; j < 64; j++) {
                int jg = jt*64 + j;
                float4 qv = *reinterpret_cast<const float4*>(&qs[j][tx*4]);
                #pragma unroll
                for (int ii = 0; ii < 4; ii++) {
                    int d = i0 + ii - jg;
                    float w = (d >= 0) ? expf(nls[j] * (float)d) : 0.0f;
                    acc[ii][0] += w * qv.x;
                    acc[ii][1] += w * qv.y;
                    acc[ii][2] += w * qv.z;
                    acc[ii][3] += w * qv.w;
                }
            }
        }
        __syncthreads();
    }

    const int kc = dt * 4 + (tx >> 2);
    const int p0 = 2 * (tx & 3);
    const int pos0 = spos(p0), pos1 = spos(p0 + 1);
    #pragma unroll
    for (int ii = 0; ii < 4; ii++) {
        long r = (long)b * SS + i0 + ii;
        uint2 w0 = split2(silu_f(acc[ii][0]), silu_f(acc[ii][1]));
        uint2 w1 = split2(silu_f(acc[ii][2]), silu_f(acc[ii][3]));
        unsigned* base = AOp + r * DIM + kc * 16;
        *reinterpret_cast<uint2*>(base + pos0) = w0;
        *reinterpret_cast<uint2*>(base + pos1) = w1;
    }
}

// ---------------- orchestration ----------------
extern "C" void kernel_launch(void* const* d_in, const int* in_sizes, int n_in,
                              void* d_out, int out_size) {
    const int*   tokens       = (const int*)  d_in[0];
    const float* emb          = (const float*)d_in[1];
    const float* decay_norm_w = (const float*)d_in[2];
    const float* lambda_w     = (const float*)d_in[3];
    const float* quantity_w   = (const float*)d_in[4];
    const float* gate_w       = (const float*)d_in[5];
    const float* output_w     = (const float*)d_in[6];
    const float* ffn_norm_w   = (const float*)d_in[7];
    const float* w_h          = (const float*)d_in[8];
    const float* w_g          = (const float*)d_in[9];
    const float* w_o          = (const float*)d_in[10];
    const float* out_norm_w   = (const float*)d_in[11];
    float* out = (float*)d_out;

    float *x, *qg, *a, *nl, *nm;
    unsigned *h_p, *f_p, *ao_p, *t_p, *hf_p, *emb_p;
    unsigned *wqg_p, *wout_p, *whh_p, *wgg_p, *wo_p;
    cudaGetSymbolAddress((void**)&x,  g_x);
    cudaGetSymbolAddress((void**)&qg, g_qg);
    cudaGetSymbolAddress((void**)&a,  g_a);
    cudaGetSymbolAddress((void**)&nl, g_nl);
    cudaGetSymbolAddress((void**)&nm, g_nlmax);
    cudaGetSymbolAddress((void**)&h_p,  g_h_p);
    cudaGetSymbolAddress((void**)&f_p,  g_f_p);
    cudaGetSymbolAddress((void**)&ao_p, g_ao_p);
    cudaGetSymbolAddress((void**)&t_p,  g_t_p);
    cudaGetSymbolAddress((void**)&hf_p, g_hf_p);
    cudaGetSymbolAddress((void**)&emb_p,g_emb_p);
    cudaGetSymbolAddress((void**)&wqg_p, g_wqg_p);
    cudaGetSymbolAddress((void**)&wout_p,g_wout_p);
    cudaGetSymbolAddress((void**)&whh_p, g_whh_p);
    cudaGetSymbolAddress((void**)&wgg_p, g_wgg_p);
    cudaGetSymbolAddress((void**)&wo_p,  g_wo_p);

    const int SM_11 = 3 * (128*32 + 128*32) * 4;   // 98304
    const int SM_10 = 3 * (128*32 + 128*16) * 4;   // 73728
    const int SM_00 = 3 * (256*16 + 128*16) * 4;   // 73728 (MT=256 plain)
    cudaFuncSetAttribute(gemm_tc<1,1,128,0>, cudaFuncAttributeMaxDynamicSharedMemorySize, SM_11);
    cudaFuncSetAttribute(gemm_tc<1,1,128,2>, cudaFuncAttributeMaxDynamicSharedMemorySize, SM_11);
    cudaFuncSetAttribute(gemm_tc<1,0,128,0>, cudaFuncAttributeMaxDynamicSharedMemorySize, SM_10);
    cudaFuncSetAttribute(gemm_tc<1,0,128,1>, cudaFuncAttributeMaxDynamicSharedMemorySize, SM_10);
    cudaFuncSetAttribute(gemm_tc<1,0,128,3>, cudaFuncAttributeMaxDynamicSharedMemorySize, SM_10);
    cudaFuncSetAttribute(gemm_tc<0,0,256,0>, cudaFuncAttributeMaxDynamicSharedMemorySize, SM_00);

    convert_all<<<CB_TOTAL, 256>>>(
        quantity_w, wqg_p, gate_w, output_w, wout_p,
        w_h, whh_p, w_g, wgg_p, w_o, wo_p, emb, emb_p, nm);

    embed_kernel<<<M_TOT * (DIM/4) / 256, 256>>>(tokens, emb, x);

    dim3 gQG (1024/128,  M_TOT/128);   // (8,  32)
    dim3 g512(DIM/128,   M_TOT/128);   // (4,  32)
    dim3 gHID(HID/128,   M_TOT/128);   // (16, 32)
    dim3 gV  (VOCAB/128, M_TOT/256);   // (250,16)  MT=256
    dim3 gattn(SS/64, DIM/64, BB);

    for (int l = 0; l < NLAYERS; l++) {
        rmsnorm_kernel<true,0><<<M_TOT, 128>>>(x, decay_norm_w + l*DIM,
                                               lambda_w + l*DIM, h_p, nl, nm + l*64);
        // [q | g] = h @ [Wq;Wg]^T  (fused, N=1024)
        gemm_tc<1,1,128,0><<<gQG, 256, SM_11>>>(h_p, wqg_p + (long)l*1024*DIM, qg,
                                                nullptr, nullptr, M_TOT, 1024, DIM, 0);
        decay_attn<<<gattn, 256>>>(qg, nl, nm + l*64, ao_p, 1024);
        // x += (silu(ao) @ Wout^T) * g
        gemm_tc<1,1,128,2><<<g512, 256, SM_11>>>(ao_p, wout_p + (long)l*DIM*DIM, x,
                                                 qg + 512, nullptr, M_TOT, DIM, DIM, 1024);
        rmsnorm_kernel<false,0><<<M_TOT, 128>>>(x, ffn_norm_w + l*DIM,
                                                nullptr, f_p, nullptr, nullptr);
        gemm_tc<1,0,128,0><<<gHID, 256, SM_10>>>(f_p, whh_p + (long)l*HID*DIM/2, a,
                                                 nullptr, nullptr, M_TOT, HID, DIM, 0);
        gemm_tc<1,0,128,3><<<gHID, 256, SM_10>>>(f_p, wgg_p + (long)l*HID*DIM/2, nullptr,
                                                 a, t_p, M_TOT, HID, DIM, HID);
        gemm_tc<1,0,128,1><<<g512, 256, SM_10>>>(t_p, wo_p + (long)l*DIM*HID/2, x,
                                                 nullptr, nullptr, M_TOT, DIM, HID, 0);
    }

    rmsnorm_kernel<false,1><<<M_TOT, 128>>>(x, out_norm_w, nullptr, hf_p, nullptr, nullptr);
    gemm_tc<0,0,256,0><<<gV, 256, SM_00>>>(hf_p, emb_p, out, nullptr, nullptr,
                                           M_TOT, VOCAB, DIM, 0);
}